// round 12
// baseline (speedup 1.0000x reference)
#include <cuda_runtime.h>
#include <cuda_bf16.h>
#include <math.h>

#define N_NODES 1024
#define KNB 16
#define CZ 128
#define CG 16
#define CS 256
#define NRBF 64
#define NE (N_NODES * KNB)   // 16384 edge rows

// scratch (no cudaMalloc allowed)
__device__ float g_nl[N_NODES * CG];
__device__ float g_nr[N_NODES * CG];
__device__ float g_tt[N_NODES * CG * CZ];   // TT[s][p][c], 8MB
__device__ float g_z[NE * CZ];              // LN'd edge feats, 8MB
__device__ float g_pre[3 * NE * CZ];        // z@{Wep,Weg,Wog}, 24MB
__device__ float g_e2[NE * CZ];             // sig(G)*(P)*mk, 8MB
__device__ float g_gz[NE * CZ];             // sig(O), 8MB
__device__ float g_mk[NE];
__device__ float g_upd[NE * CZ];            // LN'd contraction result, 8MB

__device__ __forceinline__ float sigmoidf_(float x) {
    return 1.0f / (1.0f + __expf(-x));
}

// --- input-encoding sniffers ---
__device__ __forceinline__ bool eidx_is_i64(const void* e) {
    const long long* e64 = (const long long*)e;
    bool is64 = true;
#pragma unroll
    for (int i = 0; i < 4; i++)
        if ((unsigned long long)e64[i] >= 1024ull) is64 = false;
    return is64;
}
__device__ __forceinline__ int load_idx(const void* e, bool is64, int idx) {
    return is64 ? (int)((const long long*)e)[idx] : ((const int*)e)[idx];
}
__device__ __forceinline__ bool mask_true(const void* rm, int s) {
    const unsigned int w0 = ((const unsigned int*)rm)[0];
    const unsigned int w1 = ((const unsigned int*)rm)[1];
    if (w0 == 0x3F800000u) return ((const float*)rm)[s] != 0.0f;
    if ((w0 & 0xFFFFFF00u) != 0u) return ((const unsigned char*)rm)[s] != 0;
    const unsigned int w3 = ((const unsigned int*)rm)[3];
    if (w1 == 0u && w3 == 0u) return ((const long long*)rm)[s] != 0;
    return ((const int*)rm)[s] != 0;
}

// K1: nl = nf @ Wl + bl ; nr = nf @ Wr + br
__global__ __launch_bounds__(256)
void node_proj_kernel(const float* __restrict__ nf,
                      const float* __restrict__ Wl, const float* __restrict__ bl,
                      const float* __restrict__ Wr, const float* __restrict__ br) {
    __shared__ float x[CS];
    const int n = blockIdx.x, t = threadIdx.x;
    x[t] = nf[n * CS + t];
    __syncthreads();
    const int o = t >> 3, l8 = t & 7;
    const int cc = o & 15, sel = o >> 4;
    const float* W = sel ? Wr : Wl;
    float s = 0.f;
    for (int i = l8; i < CS; i += 8) s += x[i] * W[i * CG + cc];
#pragma unroll
    for (int off = 4; off; off >>= 1) s += __shfl_down_sync(0xffffffffu, s, off, 8);
    if (l8 == 0) {
        float bias = sel ? br[cc] : bl[cc];
        (sel ? g_nr : g_nl)[n * CG + cc] = s + bias;
    }
}

// K2: TT[s][p][c] = sum_q nr[s][q] * Wdg[(p*16+q)][c]
__global__ __launch_bounds__(256)
void tt_kernel(const float* __restrict__ Wdg) {
    __shared__ float bq[CG];
    const int s = blockIdx.x, t = threadIdx.x;
    if (t < CG) bq[t] = g_nr[s * CG + t];
    __syncthreads();
    const int c = t & 127, ph = t >> 7;
    float bl_[CG];
#pragma unroll
    for (int q = 0; q < CG; q++) bl_[q] = bq[q];
#pragma unroll
    for (int pp = 0; pp < 8; pp++) {
        int p = ph * 8 + pp;
        float acc = 0.f;
#pragma unroll
        for (int q = 0; q < CG; q++)
            acc += bl_[q] * Wdg[(p * CG + q) * CZ + c];
        g_tt[((size_t)s * CG + p) * CZ + c] = acc;
    }
}

// K3: g_z = LayerNorm(ef) per row; one warp per row
__global__ __launch_bounds__(256)
void ln_kernel(const float* __restrict__ ef,
               const float* __restrict__ ln_g, const float* __restrict__ ln_b) {
    const int t = threadIdx.x, lane = t & 31, w = t >> 5;
    const int r = blockIdx.x * 8 + w;
    const float* row = ef + (size_t)r * CZ;
    float v[4];
#pragma unroll
    for (int i = 0; i < 4; i++) v[i] = row[lane + 32 * i];
    float s = v[0] + v[1] + v[2] + v[3];
    float ss = v[0] * v[0] + v[1] * v[1] + v[2] * v[2] + v[3] * v[3];
#pragma unroll
    for (int off = 16; off; off >>= 1) {
        s  += __shfl_xor_sync(0xffffffffu, s, off);
        ss += __shfl_xor_sync(0xffffffffu, ss, off);
    }
    float m = s * (1.f / 128.f);
    float var = ss * (1.f / 128.f) - m * m;
    float inv = rsqrtf(var + 1e-5f);
#pragma unroll
    for (int i = 0; i < 4; i++) {
        int cc = lane + 32 * i;
        g_z[(size_t)r * CZ + cc] = (v[i] - m) * inv * ln_g[cc] + ln_b[cc];
    }
}

// K4: g_pre[w] = g_z @ W[w]   (128-row M-tiles, 8x8 microtile)
__global__ __launch_bounds__(256, 2)
void gemm3_kernel(const float* __restrict__ Wp, const float* __restrict__ Wg,
                  const float* __restrict__ Wo) {
    __shared__ float Ast[32][132];   // A chunk, transposed [k][m]
    __shared__ float Bs[32][CZ];     // B chunk [k][n]
    const int m0 = blockIdx.x * 128;
    const int wsel = blockIdx.y;
    const float* B = (wsel == 0) ? Wp : (wsel == 1 ? Wg : Wo);
    float* C = g_pre + (size_t)wsel * NE * CZ;
    const int t = threadIdx.x;
    const int tx = t & 15, ty = t >> 4;
    float acc[8][8];
#pragma unroll
    for (int i = 0; i < 8; i++)
#pragma unroll
        for (int j = 0; j < 8; j++) acc[i][j] = 0.f;

#pragma unroll 1
    for (int kc = 0; kc < CZ; kc += 32) {
#pragma unroll
        for (int i = 0; i < 4; i++) {
            int idx = t + 256 * i;          // 0..1023
            int r = idx >> 3, c4 = idx & 7; // 8 float4 per 32-float row
            float4 v = *reinterpret_cast<const float4*>(
                &g_z[(size_t)(m0 + r) * CZ + kc + c4 * 4]);
            Ast[c4 * 4 + 0][r] = v.x; Ast[c4 * 4 + 1][r] = v.y;
            Ast[c4 * 4 + 2][r] = v.z; Ast[c4 * 4 + 3][r] = v.w;
        }
#pragma unroll
        for (int i = 0; i < 4; i++) {
            int idx = t + 256 * i;
            int r = idx >> 5, c4 = idx & 31;   // 32 float4 per 128-float row
            *reinterpret_cast<float4*>(&Bs[r][c4 * 4]) =
                *reinterpret_cast<const float4*>(&B[(size_t)(kc + r) * CZ + c4 * 4]);
        }
        __syncthreads();
#pragma unroll 4
        for (int kk = 0; kk < 32; kk++) {
            float a[8], b[8];
            *reinterpret_cast<float4*>(&a[0]) = *reinterpret_cast<const float4*>(&Ast[kk][ty * 8]);
            *reinterpret_cast<float4*>(&a[4]) = *reinterpret_cast<const float4*>(&Ast[kk][ty * 8 + 4]);
            *reinterpret_cast<float4*>(&b[0]) = *reinterpret_cast<const float4*>(&Bs[kk][tx * 8]);
            *reinterpret_cast<float4*>(&b[4]) = *reinterpret_cast<const float4*>(&Bs[kk][tx * 8 + 4]);
#pragma unroll
            for (int i = 0; i < 8; i++)
#pragma unroll
                for (int j = 0; j < 8; j++) acc[i][j] += a[i] * b[j];
        }
        __syncthreads();
    }
#pragma unroll
    for (int i = 0; i < 8; i++) {
        float4 o0 = make_float4(acc[i][0], acc[i][1], acc[i][2], acc[i][3]);
        float4 o1 = make_float4(acc[i][4], acc[i][5], acc[i][6], acc[i][7]);
        size_t base = (size_t)(m0 + ty * 8 + i) * CZ + tx * 8;
        *reinterpret_cast<float4*>(&C[base]) = o0;
        *reinterpret_cast<float4*>(&C[base + 4]) = o1;
    }
}

// K5: e2 = sig(G+beg)*(P+bep)*mk ; gz = sig(O+bog) ; g_mk
__global__ __launch_bounds__(256)
void epi_kernel(const float* __restrict__ bep, const float* __restrict__ beg,
                const float* __restrict__ bog,
                const void* __restrict__ eidx, const void* __restrict__ rm) {
    const int idx = blockIdx.x * 256 + threadIdx.x;   // float4 index
    const int m = idx >> 5, c4 = idx & 31, c = c4 * 4;
    bool is64 = eidx_is_i64(eidx);
    int s = load_idx(eidx, is64, m);
    float mk = (mask_true(rm, s) && mask_true(rm, m >> 4)) ? 1.f : 0.f;
    if (c4 == 0) g_mk[m] = mk;
    size_t off = (size_t)m * CZ + c;
    float4 P = *reinterpret_cast<const float4*>(&g_pre[off]);
    float4 G = *reinterpret_cast<const float4*>(&g_pre[(size_t)NE * CZ + off]);
    float4 O = *reinterpret_cast<const float4*>(&g_pre[2 * (size_t)NE * CZ + off]);
    float4 bp = *reinterpret_cast<const float4*>(&bep[c]);
    float4 bg = *reinterpret_cast<const float4*>(&beg[c]);
    float4 bo = *reinterpret_cast<const float4*>(&bog[c]);
    float4 e2, gz;
    e2.x = sigmoidf_(G.x + bg.x) * (P.x + bp.x) * mk;
    e2.y = sigmoidf_(G.y + bg.y) * (P.y + bp.y) * mk;
    e2.z = sigmoidf_(G.z + bg.z) * (P.z + bp.z) * mk;
    e2.w = sigmoidf_(G.w + bg.w) * (P.w + bp.w) * mk;
    gz.x = sigmoidf_(O.x + bo.x); gz.y = sigmoidf_(O.y + bo.y);
    gz.z = sigmoidf_(O.z + bo.z); gz.w = sigmoidf_(O.w + bo.w);
    *reinterpret_cast<float4*>(&g_e2[off]) = e2;
    *reinterpret_cast<float4*>(&g_gz[off]) = gz;
}

// K6: triangle contraction + output LN -> g_upd
struct __align__(16) TriSmem {
    float zu[KNB][CZ];     // upd buffer
    float e2s[KNB][CZ];
    float wdp[NRBF][CZ];   // 32KB Wdp table
    float rbf[256][8];
    int   r0[256];
    float a[KNB][CG];
    float tp[KNB][4];
    int   src[KNB];
};

__global__ __launch_bounds__(256, 3)
void tri_kernel(const float* __restrict__ trans,
                const float* __restrict__ bdg,
                const float* __restrict__ Wdp, const float* __restrict__ bdp,
                const float* __restrict__ lno_g, const float* __restrict__ lno_b,
                const void* __restrict__ eidx) {
    extern __shared__ char smem_raw[];
    TriSmem& sm = *reinterpret_cast<TriSmem*>(smem_raw);

    const int n = blockIdx.x;
    const int t = threadIdx.x;
    const int lane = t & 31, w = t >> 5;
    const int c = t & 127, g = t >> 7;
    const int jb = g * 8;

    // Wdp -> smem (independent of src)
    {
        const float4* src4 = reinterpret_cast<const float4*>(Wdp);
        float4* dst4 = reinterpret_cast<float4*>(&sm.wdp[0][0]);
#pragma unroll
        for (int i = 0; i < 8; i++) dst4[t + 256 * i] = src4[t + 256 * i];
    }
    if (t < KNB) {
        bool is64 = eidx_is_i64(eidx);
        sm.src[t] = load_idx(eidx, is64, n * KNB + t);
    }
    __syncthreads();

    // a = nl[src], positions; e2 rows -> smem
    {
        int k = t >> 4, p = t & 15;
        int s = sm.src[k];
        sm.a[k][p] = g_nl[s * CG + p];
        if (p < 3) sm.tp[k][p] = trans[s * 3 + p];
    }
    {
        const float4* e4 = reinterpret_cast<const float4*>(&g_e2[(size_t)n * KNB * CZ]);
        float4* d4 = reinterpret_cast<float4*>(&sm.e2s[0][0]);
        d4[t] = e4[t]; d4[t + 256] = e4[t + 256];
    }
    // early TT prefetch for k=0
    float ttc[16];
    {
        const float* p0 = &g_tt[(size_t)sm.src[0] * (CG * CZ) + c];
#pragma unroll
        for (int p = 0; p < 16; p++) ttc[p] = p0[p * CZ];
    }
    __syncthreads();

    // RBF windows per pair
    {
        int j = t >> 4, k = t & 15;
        float dx = sm.tp[j][0] - sm.tp[k][0] + 1e-8f;
        float dy = sm.tp[j][1] - sm.tp[k][1] + 1e-8f;
        float dz = sm.tp[j][2] - sm.tp[k][2] + 1e-8f;
        float d = sqrtf(dx * dx + dy * dy + dz * dz);
        const float STEP = 20.f / 63.f;
        const float INVS = 1.f / 0.3125f;
        int r0 = (int)floorf(d * (63.f / 20.f)) - 3;
        r0 = r0 < 0 ? 0 : (r0 > 56 ? 56 : r0);
#pragma unroll
        for (int i = 0; i < 8; i++) {
            float mu = (float)(r0 + i) * STEP;
            float x = (d - mu) * INVS;
            sm.rbf[t][i] = __expf(-x * x);
        }
        sm.r0[t] = r0;
    }
    __syncthreads();

    // contraction: thread (c,g) owns rows jb..jb+7, loops all 16 k
    float updp[8];
#pragma unroll
    for (int jj = 0; jj < 8; jj++) updp[jj] = 0.f;
    const float bdgc = bdg[c], bdpc = bdp[c];

#pragma unroll 1
    for (int k = 0; k < 16; k++) {
        float ttn[16];
        if (k < 15) {
            const float* pn = &g_tt[(size_t)sm.src[k + 1] * (CG * CZ) + c];
#pragma unroll
            for (int p = 0; p < 16; p++) ttn[p] = pn[p * CZ];
        }
        const float e2k = sm.e2s[k][c];
#pragma unroll
        for (int jj = 0; jj < 8; jj++) {
            const int j = jb + jj;
            float4 a0 = *reinterpret_cast<const float4*>(&sm.a[j][0]);
            float4 a1 = *reinterpret_cast<const float4*>(&sm.a[j][4]);
            float4 a2 = *reinterpret_cast<const float4*>(&sm.a[j][8]);
            float4 a3 = *reinterpret_cast<const float4*>(&sm.a[j][12]);
            float gate = bdgc
                + a0.x * ttc[0]  + a0.y * ttc[1]  + a0.z * ttc[2]  + a0.w * ttc[3]
                + a1.x * ttc[4]  + a1.y * ttc[5]  + a1.z * ttc[6]  + a1.w * ttc[7]
                + a2.x * ttc[8]  + a2.y * ttc[9]  + a2.z * ttc[10] + a2.w * ttc[11]
                + a3.x * ttc[12] + a3.y * ttc[13] + a3.z * ttc[14] + a3.w * ttc[15];
            const int pr = j * 16 + k;
            float4 rv0 = *reinterpret_cast<const float4*>(&sm.rbf[pr][0]);
            float4 rv1 = *reinterpret_cast<const float4*>(&sm.rbf[pr][4]);
            const float* wp = &sm.wdp[sm.r0[pr]][c];
            float df = bdpc
                + rv0.x * wp[0 * CZ] + rv0.y * wp[1 * CZ]
                + rv0.z * wp[2 * CZ] + rv0.w * wp[3 * CZ]
                + rv1.x * wp[4 * CZ] + rv1.y * wp[5 * CZ]
                + rv1.z * wp[6 * CZ] + rv1.w * wp[7 * CZ];
            updp[jj] += sigmoidf_(gate) * df * e2k;
        }
        if (k < 15) {
#pragma unroll
            for (int p = 0; p < 16; p++) ttc[p] = ttn[p];
        }
    }
#pragma unroll
    for (int jj = 0; jj < 8; jj++) sm.zu[jb + jj][c] = updp[jj];
    __syncthreads();

    // LayerNorm(upd) -> g_upd
#pragma unroll
    for (int rr = 0; rr < 2; rr++) {
        int r = 2 * w + rr;
        float v[4];
#pragma unroll
        for (int i = 0; i < 4; i++) v[i] = sm.zu[r][lane + 32 * i];
        float s = v[0] + v[1] + v[2] + v[3];
        float ss = v[0] * v[0] + v[1] * v[1] + v[2] * v[2] + v[3] * v[3];
#pragma unroll
        for (int off = 16; off; off >>= 1) {
            s  += __shfl_xor_sync(0xffffffffu, s, off);
            ss += __shfl_xor_sync(0xffffffffu, ss, off);
        }
        float m = s * (1.f / 128.f);
        float var = ss * (1.f / 128.f) - m * m;
        float inv = rsqrtf(var + 1e-5f);
#pragma unroll
        for (int i = 0; i < 4; i++) {
            int cc = lane + 32 * i;
            g_upd[((size_t)n * KNB + r) * CZ + cc] =
                (v[i] - m) * inv * lno_g[cc] + lno_b[cc];
        }
    }
}

// K7: out = (g_upd @ Wout + bout) * gz * mk
__global__ __launch_bounds__(256, 2)
void wout_kernel(const float* __restrict__ Wout, const float* __restrict__ bout,
                 float* __restrict__ out) {
    __shared__ float Ast[32][132];
    __shared__ float Bs[32][CZ];
    const int m0 = blockIdx.x * 128;
    const int t = threadIdx.x;
    const int tx = t & 15, ty = t >> 4;
    float acc[8][8];
#pragma unroll
    for (int i = 0; i < 8; i++)
#pragma unroll
        for (int j = 0; j < 8; j++) acc[i][j] = 0.f;

#pragma unroll 1
    for (int kc = 0; kc < CZ; kc += 32) {
#pragma unroll
        for (int i = 0; i < 4; i++) {
            int idx = t + 256 * i;
            int r = idx >> 3, c4 = idx & 7;
            float4 v = *reinterpret_cast<const float4*>(
                &g_upd[(size_t)(m0 + r) * CZ + kc + c4 * 4]);
            Ast[c4 * 4 + 0][r] = v.x; Ast[c4 * 4 + 1][r] = v.y;
            Ast[c4 * 4 + 2][r] = v.z; Ast[c4 * 4 + 3][r] = v.w;
        }
#pragma unroll
        for (int i = 0; i < 4; i++) {
            int idx = t + 256 * i;
            int r = idx >> 5, c4 = idx & 31;
            *reinterpret_cast<float4*>(&Bs[r][c4 * 4]) =
                *reinterpret_cast<const float4*>(&Wout[(size_t)(kc + r) * CZ + c4 * 4]);
        }
        __syncthreads();
#pragma unroll 4
        for (int kk = 0; kk < 32; kk++) {
            float a[8], b[8];
            *reinterpret_cast<float4*>(&a[0]) = *reinterpret_cast<const float4*>(&Ast[kk][ty * 8]);
            *reinterpret_cast<float4*>(&a[4]) = *reinterpret_cast<const float4*>(&Ast[kk][ty * 8 + 4]);
            *reinterpret_cast<float4*>(&b[0]) = *reinterpret_cast<const float4*>(&Bs[kk][tx * 8]);
            *reinterpret_cast<float4*>(&b[4]) = *reinterpret_cast<const float4*>(&Bs[kk][tx * 8 + 4]);
#pragma unroll
            for (int i = 0; i < 8; i++)
#pragma unroll
                for (int j = 0; j < 8; j++) acc[i][j] += a[i] * b[j];
        }
        __syncthreads();
    }
    float bo[8];
#pragma unroll
    for (int j = 0; j < 8; j++) bo[j] = bout[tx * 8 + j];
#pragma unroll
    for (int i = 0; i < 8; i++) {
        int m = m0 + ty * 8 + i;
        float mkv = g_mk[m];
        size_t base = (size_t)m * CZ + tx * 8;
        float4 gz0 = *reinterpret_cast<const float4*>(&g_gz[base]);
        float4 gz1 = *reinterpret_cast<const float4*>(&g_gz[base + 4]);
        float4 o0, o1;
        o0.x = (acc[i][0] + bo[0]) * gz0.x * mkv;
        o0.y = (acc[i][1] + bo[1]) * gz0.y * mkv;
        o0.z = (acc[i][2] + bo[2]) * gz0.z * mkv;
        o0.w = (acc[i][3] + bo[3]) * gz0.w * mkv;
        o1.x = (acc[i][4] + bo[4]) * gz1.x * mkv;
        o1.y = (acc[i][5] + bo[5]) * gz1.y * mkv;
        o1.z = (acc[i][6] + bo[6]) * gz1.z * mkv;
        o1.w = (acc[i][7] + bo[7]) * gz1.w * mkv;
        *reinterpret_cast<float4*>(&out[base]) = o0;
        *reinterpret_cast<float4*>(&out[base + 4]) = o1;
    }
}

extern "C" void kernel_launch(void* const* d_in, const int* in_sizes, int n_in,
                              void* d_out, int out_size) {
    const float* node_features = (const float*)d_in[0];
    const float* trans         = (const float*)d_in[1];
    const float* edge_features = (const float*)d_in[2];
    const float* ln_g  = (const float*)d_in[3];
    const float* ln_b  = (const float*)d_in[4];
    const float* Wl    = (const float*)d_in[5];
    const float* bl    = (const float*)d_in[6];
    const float* Wr    = (const float*)d_in[7];
    const float* br    = (const float*)d_in[8];
    const float* Wep   = (const float*)d_in[9];
    const float* bep   = (const float*)d_in[10];
    const float* Weg   = (const float*)d_in[11];
    const float* beg   = (const float*)d_in[12];
    const float* Wdg   = (const float*)d_in[13];
    const float* bdg   = (const float*)d_in[14];
    const float* Wdp   = (const float*)d_in[15];
    const float* bdp   = (const float*)d_in[16];
    const float* lno_g = (const float*)d_in[17];
    const float* lno_b = (const float*)d_in[18];
    const float* Wout  = (const float*)d_in[19];
    const float* bout  = (const float*)d_in[20];
    const float* Wog   = (const float*)d_in[21];
    const float* bog   = (const float*)d_in[22];
    const void* edge_index = d_in[23];
    const void* res_mask   = d_in[25];

    float* outp = (float*)d_out;

    static_assert(sizeof(TriSmem) < 62 * 1024, "smem too big for 3 CTAs");
    cudaFuncSetAttribute(tri_kernel, cudaFuncAttributeMaxDynamicSharedMemorySize,
                         (int)sizeof(TriSmem));

    node_proj_kernel<<<N_NODES, 256>>>(node_features, Wl, bl, Wr, br);
    tt_kernel<<<N_NODES, 256>>>(Wdg);
    ln_kernel<<<NE / 8, 256>>>(edge_features, ln_g, ln_b);
    gemm3_kernel<<<dim3(NE / 128, 3), 256>>>(Wep, Weg, Wog);
    epi_kernel<<<NE * CZ / 4 / 256, 256>>>(bep, beg, bog, edge_index, res_mask);
    tri_kernel<<<N_NODES, 256, sizeof(TriSmem)>>>(trans, bdg, Wdp, bdp,
                                                  lno_g, lno_b, edge_index);
    wout_kernel<<<NE / 128, 256>>>(Wout, bout, outp);
}